// round 1
// baseline (speedup 1.0000x reference)
#include <cuda_runtime.h>
#include <cuda_bf16.h>
#include <math.h>

// Problem constants (fixed shapes from reference):
// B=8, CK=64, CV=512, H=W=64, HW=4096
// Mk: [B, CK, HW]   (m contiguous)
// Qk: [B, CK, HW]   (q contiguous)
// mv: [B, CV, HW]   (m contiguous)
// out:[B, CV, HW]   (q contiguous)
//
// out[b,c,q] = sum_m mv[b,c,m] * softmax_m( sum_k Mk[b,k,m]*Qk[b,k,q]*scale )

#define B_   8
#define CK_  64
#define CV_  512
#define HW_  4096
#define SCALE 0.125f   // 1/sqrt(64)

// ---------------- scratch: per-(b,q) softmax stats ----------------
__device__ float g_max[B_ * HW_];
__device__ float g_invl[B_ * HW_];

// ==================================================================
// Pass 1: per query column q, compute max_m S[m,q] and 1/sum_m exp(S-max)
// One thread owns one q. 256 threads/CTA, grid (HW/256, B).
// ==================================================================
__global__ __launch_bounds__(256, 1)
void am_pass1(const float* __restrict__ Mk, const float* __restrict__ Qk) {
    const int b = blockIdx.y;
    const int q = blockIdx.x * 256 + threadIdx.x;
    const int tid = threadIdx.x;

    // Load this thread's q column (64 features) into registers, pre-scaled.
    float qreg[CK_];
#pragma unroll
    for (int c = 0; c < CK_; c++) {
        qreg[c] = Qk[(b * CK_ + c) * HW_ + q] * SCALE;
    }

    // mk tile transposed into smem: mks[m][c], padded row of 68 floats
    // (row stride 272B = 17*16B -> float4-aligned rows)
    __shared__ float mks[64][68];

    float mx = -1e30f;
    float ssum = 0.0f;

    for (int mt = 0; mt < HW_; mt += 64) {
        __syncthreads();
        // load 64x64 tile: gmem coalesced over m, transpose into [m][c]
        for (int i = tid; i < 64 * 64; i += 256) {
            int c = i >> 6;
            int m = i & 63;
            mks[m][c] = Mk[(b * CK_ + c) * HW_ + mt + m];
        }
        __syncthreads();

#pragma unroll 4
        for (int m = 0; m < 64; m++) {
            float a0 = 0.f, a1 = 0.f, a2 = 0.f, a3 = 0.f;
            const float4* row = reinterpret_cast<const float4*>(&mks[m][0]);
#pragma unroll
            for (int c4 = 0; c4 < 16; c4++) {
                float4 v = row[c4];
                a0 = fmaf(v.x, qreg[c4 * 4 + 0], a0);
                a1 = fmaf(v.y, qreg[c4 * 4 + 1], a1);
                a2 = fmaf(v.z, qreg[c4 * 4 + 2], a2);
                a3 = fmaf(v.w, qreg[c4 * 4 + 3], a3);
            }
            float dot = (a0 + a1) + (a2 + a3);
            // branchless online softmax update
            float nm = fmaxf(mx, dot);
            ssum = ssum * __expf(mx - nm) + __expf(dot - nm);
            mx = nm;
        }
    }

    g_max[b * HW_ + q]  = mx;
    g_invl[b * HW_ + q] = 1.0f / ssum;
}

// ==================================================================
// Pass 2: fused S-recompute + exp + PV accumulate.
// CTA tile: CVT=128 channels x QT=64 queries, loop m in tiles of MT=64.
// 256 threads. Dynamic smem ~83 KB -> 2 CTAs/SM.
// Grid: (HW/64, CV/128, B) = (64, 4, 8)
// ==================================================================
#define QT  64
#define CVT 128
#define MT  64

__global__ __launch_bounds__(256, 2)
void am_pass2(const float* __restrict__ Mk, const float* __restrict__ Qk,
              const float* __restrict__ mv, float* __restrict__ out) {
    extern __shared__ float sm[];
    // layout
    float* qs  = sm;              // [c][q]  64*64
    float* mks = qs  + 64 * 64;   // [c][m]  64*64
    float* mvs = mks + 64 * 64;   // [cv][m] 128 rows, stride 65
    float* Pt  = mvs + 128 * 65;  // [m][q]  64*64
    float* smx = Pt  + 64 * 64;   // [64]
    float* sil = smx + 64;        // [64]

    const int b   = blockIdx.z;
    const int cv0 = blockIdx.y * CVT;
    const int q0  = blockIdx.x * QT;
    const int tid = threadIdx.x;

    // ---- one-time loads: q tile (scaled) + stats ----
    for (int i = tid; i < (64 * 64) / 4; i += 256) {
        int c  = i >> 4;
        int q4 = (i & 15) * 4;
        float4 v = *reinterpret_cast<const float4*>(
            &Qk[(b * CK_ + c) * HW_ + q0 + q4]);
        v.x *= SCALE; v.y *= SCALE; v.z *= SCALE; v.w *= SCALE;
        *reinterpret_cast<float4*>(&qs[c * 64 + q4]) = v;
    }
    if (tid < 64) {
        smx[tid] = g_max[b * HW_ + q0 + tid];
        sil[tid] = g_invl[b * HW_ + q0 + tid];
    }

    // thread coords (shared by both phases): 16x16 thread grid
    const int th = tid >> 4;   // 0..15 : S-phase m-group / PV-phase cv-group
    const int tq = tid & 15;   // 0..15 : q-group (4 q's)

    float acc[8][4];
#pragma unroll
    for (int i = 0; i < 8; i++)
#pragma unroll
        for (int j = 0; j < 4; j++) acc[i][j] = 0.f;

    for (int mt = 0; mt < HW_; mt += MT) {
        __syncthreads();
        // ---- load mk tile [c][m] (float4) ----
        for (int i = tid; i < (64 * 64) / 4; i += 256) {
            int c  = i >> 4;
            int m4 = (i & 15) * 4;
            float4 v = *reinterpret_cast<const float4*>(
                &Mk[(b * CK_ + c) * HW_ + mt + m4]);
            *reinterpret_cast<float4*>(&mks[c * 64 + m4]) = v;
        }
        // ---- load mv tile [cv][m] with pad-65 rows ----
        for (int i = tid; i < (128 * 64) / 4; i += 256) {
            int cv = i >> 4;
            int m4 = (i & 15) * 4;
            float4 v = *reinterpret_cast<const float4*>(
                &mv[(b * CV_ + cv0 + cv) * HW_ + mt + m4]);
            float* dst = &mvs[cv * 65 + m4];
            dst[0] = v.x; dst[1] = v.y; dst[2] = v.z; dst[3] = v.w;
        }
        __syncthreads();

        // ---- S phase: 4m x 4q register tile per thread ----
        float s[4][4];
#pragma unroll
        for (int i = 0; i < 4; i++)
#pragma unroll
            for (int j = 0; j < 4; j++) s[i][j] = 0.f;

#pragma unroll 16
        for (int c = 0; c < 64; c++) {
            float4 a = *reinterpret_cast<const float4*>(&mks[c * 64 + th * 4]);
            float4 bq = *reinterpret_cast<const float4*>(&qs[c * 64 + tq * 4]);
            float am[4] = {a.x, a.y, a.z, a.w};
            float bm[4] = {bq.x, bq.y, bq.z, bq.w};
#pragma unroll
            for (int i = 0; i < 4; i++)
#pragma unroll
                for (int j = 0; j < 4; j++)
                    s[i][j] = fmaf(am[i], bm[j], s[i][j]);
        }
        // exp + normalize, write P[m][q]
#pragma unroll
        for (int i = 0; i < 4; i++) {
            int m = th * 4 + i;
            float4 p;
            p.x = __expf(s[i][0] - smx[tq * 4 + 0]) * sil[tq * 4 + 0];
            p.y = __expf(s[i][1] - smx[tq * 4 + 1]) * sil[tq * 4 + 1];
            p.z = __expf(s[i][2] - smx[tq * 4 + 2]) * sil[tq * 4 + 2];
            p.w = __expf(s[i][3] - smx[tq * 4 + 3]) * sil[tq * 4 + 3];
            *reinterpret_cast<float4*>(&Pt[m * 64 + tq * 4]) = p;
        }
        __syncthreads();

        // ---- PV phase: 8cv x 4q per thread, loop m ----
#pragma unroll 4
        for (int m = 0; m < MT; m++) {
            float4 p = *reinterpret_cast<const float4*>(&Pt[m * 64 + tq * 4]);
#pragma unroll
            for (int i = 0; i < 8; i++) {
                float v = mvs[(th * 8 + i) * 65 + m];
                acc[i][0] = fmaf(v, p.x, acc[i][0]);
                acc[i][1] = fmaf(v, p.y, acc[i][1]);
                acc[i][2] = fmaf(v, p.z, acc[i][2]);
                acc[i][3] = fmaf(v, p.w, acc[i][3]);
            }
        }
    }

    // ---- writeback ----
#pragma unroll
    for (int i = 0; i < 8; i++) {
        int row = cv0 + th * 8 + i;
        float4 v = make_float4(acc[i][0], acc[i][1], acc[i][2], acc[i][3]);
        *reinterpret_cast<float4*>(&out[(b * CV_ + row) * HW_ + q0 + tq * 4]) = v;
    }
}

// ==================================================================
extern "C" void kernel_launch(void* const* d_in, const int* in_sizes, int n_in,
                              void* d_out, int out_size) {
    const float* Mk = (const float*)d_in[0];
    const float* Qk = (const float*)d_in[1];
    const float* mv = (const float*)d_in[2];
    float* out = (float*)d_out;

    // Pass 1: softmax stats
    am_pass1<<<dim3(HW_ / 256, B_), 256>>>(Mk, Qk);

    // Pass 2: fused attention output
    const int smem_bytes =
        (64 * 64 + 64 * 64 + 128 * 65 + 64 * 64 + 128) * (int)sizeof(float);
    static int attr_set = 0;
    (void)attr_set;
    cudaFuncSetAttribute(am_pass2, cudaFuncAttributeMaxDynamicSharedMemorySize,
                         smem_bytes);
    am_pass2<<<dim3(HW_ / QT, CV_ / CVT, B_), 256, smem_bytes>>>(Mk, Qk, mv, out);
}